// round 3
// baseline (speedup 1.0000x reference)
#include <cuda_runtime.h>

// ColorRestoration: per-row 14-tap windowed correlation + shifted-z copy.
//   y[c,h,w]   = sum_{u=w-13..w, u>=0} x[h,u+rc]*z[h,u]  /  sum z[h,u]
//   rgb[c,h,w] = z[h, w-rc]   (0 if w<rc),  rc in {3,7,10}
// Output layout: y (3,H,W) then rgb_filter (3,H,W), float32.
//
// R2: two rows per block -> 2x LDG in flight before the single __syncthreads,
// halves barrier count per byte moved; __stcs streaming stores (151MB > L2).

#define IMG_W 3072
#define IMG_H 2048
#define SEG   1024
#define HALO  16
#define SMEMN (SEG + 2 * HALO)   // 1056 floats per array per row
#define ROWS_PB 2

__device__ __forceinline__
void stage_row(const float* __restrict__ xrow, const float* __restrict__ zrow,
               float* __restrict__ sx, float* __restrict__ sz,
               int gw0, int t)
{
    #pragma unroll
    for (int v = t; v < SMEMN / 4; v += 256) {
        const int g = gw0 - HALO + 4 * v;      // float4-aligned (gw0 mult of 1024)
        float4 xv, zv;
        if (g >= 0 && g + 3 < IMG_W) {
            xv = *reinterpret_cast<const float4*>(xrow + g);
            zv = *reinterpret_cast<const float4*>(zrow + g);
        } else {
            float tx[4], tz[4];
            #pragma unroll
            for (int j = 0; j < 4; ++j) {
                const int gg = g + j;
                const bool ok = (gg >= 0) && (gg < IMG_W);
                tx[j] = ok ? xrow[gg] : 0.0f;
                tz[j] = ok ? zrow[gg] : 0.0f;
            }
            xv = make_float4(tx[0], tx[1], tx[2], tx[3]);
            zv = make_float4(tz[0], tz[1], tz[2], tz[3]);
        }
        *reinterpret_cast<float4*>(sx + 4 * v) = xv;
        *reinterpret_cast<float4*>(sz + 4 * v) = zv;
    }
}

__device__ __forceinline__
void compute_row(const float* __restrict__ sx, const float* __restrict__ sz,
                 float* __restrict__ out, int h, int gw0, int t)
{
    const int sI = HALO + 4 * t;               // shared idx of w0 (mult of 4)

    // z window: zr[j] = z[w0 - 16 + j], j = 0..19   (5 aligned LDS.128)
    float zr[20];
    #pragma unroll
    for (int q = 0; q < 5; ++q) {
        const float4 v = *reinterpret_cast<const float4*>(sz + (sI - 16) + 4 * q);
        zr[4 * q + 0] = v.x; zr[4 * q + 1] = v.y;
        zr[4 * q + 2] = v.z; zr[4 * q + 3] = v.w;
    }
    // x window: xr[j] = x[w0 - 12 + j], j = 0..27   (7 aligned LDS.128)
    float xr[28];
    #pragma unroll
    for (int q = 0; q < 7; ++q) {
        const float4 v = *reinterpret_cast<const float4*>(sx + (sI - 12) + 4 * q);
        xr[4 * q + 0] = v.x; xr[4 * q + 1] = v.y;
        xr[4 * q + 2] = v.z; xr[4 * q + 3] = v.w;
    }

    // init window sum ending at w0: u = w0-13+k, k=0..13
    float den = 0.0f, n3 = 0.0f, n7 = 0.0f, n10 = 0.0f;
    #pragma unroll
    for (int k = 0; k < 14; ++k) {
        const float zu = zr[3 + k];
        den += zu;
        n3  = fmaf(xr[k + 2], zu, n3);
        n7  = fmaf(xr[k + 6], zu, n7);
        n10 = fmaf(xr[k + 9], zu, n10);
    }

    float y3a[4], y7a[4], y10a[4], f3a[4], f7a[4], f10a[4];
    {
        const float r = 1.0f / den;
        y3a[0] = n3 * r;  y7a[0] = n7 * r;  y10a[0] = n10 * r;
        f3a[0] = zr[13];  f7a[0] = zr[9];   f10a[0] = zr[6];
    }
    // slide: add u_new = w0+i (z=zr[16+i]), drop u_old = w0+i-14 (z=zr[2+i])
    #pragma unroll
    for (int i = 1; i < 4; ++i) {
        const float zn = zr[16 + i];
        const float zo = zr[2 + i];
        den += zn - zo;
        n3  = fmaf(xr[15 + i], zn, fmaf(-xr[1 + i], zo, n3));
        n7  = fmaf(xr[19 + i], zn, fmaf(-xr[5 + i], zo, n7));
        n10 = fmaf(xr[22 + i], zn, fmaf(-xr[8 + i], zo, n10));
        const float r = 1.0f / den;
        y3a[i] = n3 * r;   y7a[i] = n7 * r;   y10a[i] = n10 * r;
        f3a[i] = zr[13 + i]; f7a[i] = zr[9 + i]; f10a[i] = zr[6 + i];
    }

    // ---- coalesced streaming float4 stores ----
    const size_t HW   = (size_t)IMG_H * IMG_W;
    const size_t base = (size_t)h * IMG_W + gw0 + 4 * t;
    __stcs(reinterpret_cast<float4*>(out + 0 * HW + base), *reinterpret_cast<float4*>(y3a));
    __stcs(reinterpret_cast<float4*>(out + 1 * HW + base), *reinterpret_cast<float4*>(y7a));
    __stcs(reinterpret_cast<float4*>(out + 2 * HW + base), *reinterpret_cast<float4*>(y10a));
    __stcs(reinterpret_cast<float4*>(out + 3 * HW + base), *reinterpret_cast<float4*>(f3a));
    __stcs(reinterpret_cast<float4*>(out + 4 * HW + base), *reinterpret_cast<float4*>(f7a));
    __stcs(reinterpret_cast<float4*>(out + 5 * HW + base), *reinterpret_cast<float4*>(f10a));
}

__global__ __launch_bounds__(256, 4)
void color_restore_kernel(const float* __restrict__ x,
                          const float* __restrict__ z,
                          float* __restrict__ out)
{
    __shared__ float sx[ROWS_PB][SMEMN];
    __shared__ float sz[ROWS_PB][SMEMN];

    const int h0  = blockIdx.y * ROWS_PB;
    const int gw0 = blockIdx.x * SEG;
    const int t   = threadIdx.x;

    // Front-batch BOTH rows' global loads before the single barrier:
    // ~2x memory requests in flight per thread vs one-row blocks.
    #pragma unroll
    for (int r = 0; r < ROWS_PB; ++r) {
        const int h = h0 + r;
        stage_row(x + (size_t)h * IMG_W, z + (size_t)h * IMG_W,
                  sx[r], sz[r], gw0, t);
    }
    __syncthreads();

    #pragma unroll
    for (int r = 0; r < ROWS_PB; ++r)
        compute_row(sx[r], sz[r], out, h0 + r, gw0, t);
}

extern "C" void kernel_launch(void* const* d_in, const int* in_sizes, int n_in,
                              void* d_out, int out_size)
{
    (void)in_sizes; (void)n_in; (void)out_size;
    const float* x = (const float*)d_in[0];
    const float* z = (const float*)d_in[1];
    float* out = (float*)d_out;

    dim3 grid(IMG_W / SEG, IMG_H / ROWS_PB);   // (3, 1024)
    color_restore_kernel<<<grid, 256>>>(x, z, out);
}

// round 4
// speedup vs baseline: 1.1089x; 1.1089x over previous
#include <cuda_runtime.h>

// ColorRestoration: per-row 14-tap windowed correlation + shifted-z copy.
//   y[c,h,w]   = sum_{u=w-13..w, u>=0} x[h,u+rc]*z[h,u]  /  sum z[h,u]
//   rgb[c,h,w] = z[h, w-rc]   (0 if w<rc),  rc in {3,7,10}
// Output layout: y (3,H,W) then rgb_filter (3,H,W), float32.
//
// R3: no shared memory, no barrier. Each thread gathers its 48-float window
// directly via aligned LDG.128 (overlap served by L1/L2), computes 4 outputs,
// streams 6 float4 stores. Phase-free -> overlapped LSU/DRAM utilization.

#define IMG_W 3072
#define IMG_H 2048
#define SEG   1024

__device__ __forceinline__
float4 ld4_guard(const float* __restrict__ row, int g)
{
    if (g >= 0 && g + 3 < IMG_W)
        return __ldg(reinterpret_cast<const float4*>(row + g));
    float t[4];
    #pragma unroll
    for (int j = 0; j < 4; ++j) {
        const int gg = g + j;
        t[j] = (gg >= 0 && gg < IMG_W) ? __ldg(row + gg) : 0.0f;
    }
    return make_float4(t[0], t[1], t[2], t[3]);
}

__global__ __launch_bounds__(256)
void color_restore_kernel(const float* __restrict__ x,
                          const float* __restrict__ z,
                          float* __restrict__ out)
{
    const int h   = blockIdx.y;
    const int gw0 = blockIdx.x * SEG;
    const int t   = threadIdx.x;
    const int w0  = gw0 + 4 * t;               // multiple of 4

    const float* __restrict__ xrow = x + (size_t)h * IMG_W;
    const float* __restrict__ zrow = z + (size_t)h * IMG_W;

    // windows: zr[j] = z[w0-16+j] j=0..19 ; xr[j] = x[w0-12+j] j=0..27
    float zr[20];
    float xr[28];

    // interior iff w0-16 >= 0 for t=0 (gw0>=16) and w0+15 < IMG_W for t=255
    const bool interior = (gw0 >= 16) && (gw0 + SEG + 11 < IMG_W);

    if (interior) {
        #pragma unroll
        for (int q = 0; q < 5; ++q) {
            const float4 v = __ldg(reinterpret_cast<const float4*>(zrow + (w0 - 16) + 4 * q));
            zr[4*q+0] = v.x; zr[4*q+1] = v.y; zr[4*q+2] = v.z; zr[4*q+3] = v.w;
        }
        #pragma unroll
        for (int q = 0; q < 7; ++q) {
            const float4 v = __ldg(reinterpret_cast<const float4*>(xrow + (w0 - 12) + 4 * q));
            xr[4*q+0] = v.x; xr[4*q+1] = v.y; xr[4*q+2] = v.z; xr[4*q+3] = v.w;
        }
    } else {
        #pragma unroll
        for (int q = 0; q < 5; ++q) {
            const float4 v = ld4_guard(zrow, (w0 - 16) + 4 * q);
            zr[4*q+0] = v.x; zr[4*q+1] = v.y; zr[4*q+2] = v.z; zr[4*q+3] = v.w;
        }
        #pragma unroll
        for (int q = 0; q < 7; ++q) {
            const float4 v = ld4_guard(xrow, (w0 - 12) + 4 * q);
            xr[4*q+0] = v.x; xr[4*q+1] = v.y; xr[4*q+2] = v.z; xr[4*q+3] = v.w;
        }
    }

    // init window sum ending at w0: u = w0-13+k, k=0..13
    //   z[u] -> zr[3+k] ; x[u+3] -> xr[k+2] ; x[u+7] -> xr[k+6] ; x[u+10] -> xr[k+9]
    float den = 0.0f, n3 = 0.0f, n7 = 0.0f, n10 = 0.0f;
    #pragma unroll
    for (int k = 0; k < 14; ++k) {
        const float zu = zr[3 + k];
        den += zu;
        n3  = fmaf(xr[k + 2], zu, n3);
        n7  = fmaf(xr[k + 6], zu, n7);
        n10 = fmaf(xr[k + 9], zu, n10);
    }

    float y3a[4], y7a[4], y10a[4], f3a[4], f7a[4], f10a[4];
    {
        const float r = 1.0f / den;
        y3a[0] = n3 * r;  y7a[0] = n7 * r;  y10a[0] = n10 * r;
        f3a[0] = zr[13];  f7a[0] = zr[9];   f10a[0] = zr[6];
    }
    // slide: add u_new = w0+i (z=zr[16+i]), drop u_old = w0+i-14 (z=zr[2+i])
    #pragma unroll
    for (int i = 1; i < 4; ++i) {
        const float zn = zr[16 + i];
        const float zo = zr[2 + i];
        den += zn - zo;
        n3  = fmaf(xr[15 + i], zn, fmaf(-xr[1 + i], zo, n3));
        n7  = fmaf(xr[19 + i], zn, fmaf(-xr[5 + i], zo, n7));
        n10 = fmaf(xr[22 + i], zn, fmaf(-xr[8 + i], zo, n10));
        const float r = 1.0f / den;
        y3a[i] = n3 * r;   y7a[i] = n7 * r;   y10a[i] = n10 * r;
        f3a[i] = zr[13 + i]; f7a[i] = zr[9 + i]; f10a[i] = zr[6 + i];
    }

    // ---- coalesced streaming float4 stores ----
    const size_t HW   = (size_t)IMG_H * IMG_W;
    const size_t base = (size_t)h * IMG_W + w0;
    __stcs(reinterpret_cast<float4*>(out + 0 * HW + base), *reinterpret_cast<float4*>(y3a));
    __stcs(reinterpret_cast<float4*>(out + 1 * HW + base), *reinterpret_cast<float4*>(y7a));
    __stcs(reinterpret_cast<float4*>(out + 2 * HW + base), *reinterpret_cast<float4*>(y10a));
    __stcs(reinterpret_cast<float4*>(out + 3 * HW + base), *reinterpret_cast<float4*>(f3a));
    __stcs(reinterpret_cast<float4*>(out + 4 * HW + base), *reinterpret_cast<float4*>(f7a));
    __stcs(reinterpret_cast<float4*>(out + 5 * HW + base), *reinterpret_cast<float4*>(f10a));
}

extern "C" void kernel_launch(void* const* d_in, const int* in_sizes, int n_in,
                              void* d_out, int out_size)
{
    (void)in_sizes; (void)n_in; (void)out_size;
    const float* x = (const float*)d_in[0];
    const float* z = (const float*)d_in[1];
    float* out = (float*)d_out;

    dim3 grid(IMG_W / SEG, IMG_H);   // (3, 2048)
    color_restore_kernel<<<grid, 256>>>(x, z, out);
}

// round 5
// speedup vs baseline: 1.1159x; 1.0063x over previous
#include <cuda_runtime.h>

// ColorRestoration: per-row 14-tap windowed correlation + shifted-z copy.
//   y[c,h,w]   = sum_{u=w-13..w, u>=0} x[h,u+rc]*z[h,u]  /  sum z[h,u]
//   rgb[c,h,w] = z[h, w-rc]   (0 if w<rc),  rc in {3,7,10}
// Output layout: y (3,H,W) then rgb_filter (3,H,W), float32.
//
// R4: per-WARP smem staging. Each warp stages its 160-float x/z slice with
// <=4 non-redundant LDG.128 per lane, __syncwarp() (no block barrier), then
// conflict-free LDS.128 window gathers. Cuts L1tex wavefronts ~3x vs R3's
// redundant direct loads -> lower queue-induced load latency.

#define IMG_W 3072
#define IMG_H 2048
#define SEG   1024
#define WSPAN 160            // floats staged per warp per array: [base-16, base+144)

__device__ __forceinline__
float4 ld4_guard(const float* __restrict__ row, int g)
{
    if (g >= 0 && g + 3 < IMG_W)
        return __ldg(reinterpret_cast<const float4*>(row + g));
    float t[4];
    #pragma unroll
    for (int j = 0; j < 4; ++j) {
        const int gg = g + j;
        t[j] = (gg >= 0 && gg < IMG_W) ? __ldg(row + gg) : 0.0f;
    }
    return make_float4(t[0], t[1], t[2], t[3]);
}

__global__ __launch_bounds__(256, 4)
void color_restore_kernel(const float* __restrict__ x,
                          const float* __restrict__ z,
                          float* __restrict__ out)
{
    __shared__ float sx[8][WSPAN];
    __shared__ float sz[8][WSPAN];

    const int h    = blockIdx.y;
    const int gw0  = blockIdx.x * SEG;
    const int t    = threadIdx.x;
    const int wid  = t >> 5;
    const int lane = t & 31;

    const float* __restrict__ xrow = x + (size_t)h * IMG_W;
    const float* __restrict__ zrow = z + (size_t)h * IMG_W;

    const int base = gw0 + (wid << 7);          // warp's first output column
    float* __restrict__ swx = sx[wid];
    float* __restrict__ swz = sz[wid];

    // ---- stage warp slice: chunks c=0..39, chunk c at global g=base-16+4c ----
    // lane loads chunk 'lane'; lanes 0..7 also load chunk 32+lane.
    const bool winterior = (base >= 16) && (base + 143 < IMG_W);
    if (winterior) {
        const float4 xv = __ldg(reinterpret_cast<const float4*>(xrow + base - 16 + 4 * lane));
        const float4 zv = __ldg(reinterpret_cast<const float4*>(zrow + base - 16 + 4 * lane));
        float4 xv2, zv2;
        if (lane < 8) {
            xv2 = __ldg(reinterpret_cast<const float4*>(xrow + base + 112 + 4 * lane));
            zv2 = __ldg(reinterpret_cast<const float4*>(zrow + base + 112 + 4 * lane));
        }
        reinterpret_cast<float4*>(swx)[lane] = xv;
        reinterpret_cast<float4*>(swz)[lane] = zv;
        if (lane < 8) {
            reinterpret_cast<float4*>(swx)[32 + lane] = xv2;
            reinterpret_cast<float4*>(swz)[32 + lane] = zv2;
        }
    } else {
        const float4 xv = ld4_guard(xrow, base - 16 + 4 * lane);
        const float4 zv = ld4_guard(zrow, base - 16 + 4 * lane);
        float4 xv2, zv2;
        if (lane < 8) {
            xv2 = ld4_guard(xrow, base + 112 + 4 * lane);
            zv2 = ld4_guard(zrow, base + 112 + 4 * lane);
        }
        reinterpret_cast<float4*>(swx)[lane] = xv;
        reinterpret_cast<float4*>(swz)[lane] = zv;
        if (lane < 8) {
            reinterpret_cast<float4*>(swx)[32 + lane] = xv2;
            reinterpret_cast<float4*>(swz)[32 + lane] = zv2;
        }
    }
    __syncwarp();

    // ---- per-thread windows from warp slice ----
    // w0 = base + 4*lane; slice index of w0 is 16 + 4*lane.
    const int sI = 16 + 4 * lane;

    // zr[j] = z[w0-16+j], j=0..19  (5 aligned LDS.128)
    float zr[20];
    #pragma unroll
    for (int q = 0; q < 5; ++q) {
        const float4 v = *reinterpret_cast<const float4*>(swz + (sI - 16) + 4 * q);
        zr[4*q+0] = v.x; zr[4*q+1] = v.y; zr[4*q+2] = v.z; zr[4*q+3] = v.w;
    }
    // xr[j] = x[w0-12+j], j=0..27  (7 aligned LDS.128)
    float xr[28];
    #pragma unroll
    for (int q = 0; q < 7; ++q) {
        const float4 v = *reinterpret_cast<const float4*>(swx + (sI - 12) + 4 * q);
        xr[4*q+0] = v.x; xr[4*q+1] = v.y; xr[4*q+2] = v.z; xr[4*q+3] = v.w;
    }

    // init window sum ending at w0: u = w0-13+k, k=0..13
    //   z[u] -> zr[3+k] ; x[u+3] -> xr[k+2] ; x[u+7] -> xr[k+6] ; x[u+10] -> xr[k+9]
    float den = 0.0f, n3 = 0.0f, n7 = 0.0f, n10 = 0.0f;
    #pragma unroll
    for (int k = 0; k < 14; ++k) {
        const float zu = zr[3 + k];
        den += zu;
        n3  = fmaf(xr[k + 2], zu, n3);
        n7  = fmaf(xr[k + 6], zu, n7);
        n10 = fmaf(xr[k + 9], zu, n10);
    }

    float y3a[4], y7a[4], y10a[4], f3a[4], f7a[4], f10a[4];
    {
        const float r = 1.0f / den;
        y3a[0] = n3 * r;  y7a[0] = n7 * r;  y10a[0] = n10 * r;
        f3a[0] = zr[13];  f7a[0] = zr[9];   f10a[0] = zr[6];
    }
    // slide: add u_new = w0+i (z=zr[16+i]), drop u_old = w0+i-14 (z=zr[2+i])
    #pragma unroll
    for (int i = 1; i < 4; ++i) {
        const float zn = zr[16 + i];
        const float zo = zr[2 + i];
        den += zn - zo;
        n3  = fmaf(xr[15 + i], zn, fmaf(-xr[1 + i], zo, n3));
        n7  = fmaf(xr[19 + i], zn, fmaf(-xr[5 + i], zo, n7));
        n10 = fmaf(xr[22 + i], zn, fmaf(-xr[8 + i], zo, n10));
        const float r = 1.0f / den;
        y3a[i] = n3 * r;   y7a[i] = n7 * r;   y10a[i] = n10 * r;
        f3a[i] = zr[13 + i]; f7a[i] = zr[9 + i]; f10a[i] = zr[6 + i];
    }

    // ---- coalesced streaming float4 stores ----
    const size_t HW   = (size_t)IMG_H * IMG_W;
    const size_t basо = (size_t)h * IMG_W + base + 4 * lane;
    __stcs(reinterpret_cast<float4*>(out + 0 * HW + basо), *reinterpret_cast<float4*>(y3a));
    __stcs(reinterpret_cast<float4*>(out + 1 * HW + basо), *reinterpret_cast<float4*>(y7a));
    __stcs(reinterpret_cast<float4*>(out + 2 * HW + basо), *reinterpret_cast<float4*>(y10a));
    __stcs(reinterpret_cast<float4*>(out + 3 * HW + basо), *reinterpret_cast<float4*>(f3a));
    __stcs(reinterpret_cast<float4*>(out + 4 * HW + basо), *reinterpret_cast<float4*>(f7a));
    __stcs(reinterpret_cast<float4*>(out + 5 * HW + basо), *reinterpret_cast<float4*>(f10a));
}

extern "C" void kernel_launch(void* const* d_in, const int* in_sizes, int n_in,
                              void* d_out, int out_size)
{
    (void)in_sizes; (void)n_in; (void)out_size;
    const float* x = (const float*)d_in[0];
    const float* z = (const float*)d_in[1];
    float* out = (float*)d_out;

    dim3 grid(IMG_W / SEG, IMG_H);   // (3, 2048)
    color_restore_kernel<<<grid, 256>>>(x, z, out);
}

// round 6
// speedup vs baseline: 1.1536x; 1.0337x over previous
#include <cuda_runtime.h>

// ColorRestoration: per-row 14-tap windowed correlation + shifted-z copy.
//   y[c,h,w]   = sum_{u=w-13..w, u>=0} x[h,u+rc]*z[h,u]  /  sum z[h,u]
//   rgb[c,h,w] = z[h, w-rc]   (0 if w<rc),  rc in {3,7,10}
// Output layout: y (3,H,W) then rgb_filter (3,H,W), float32.
//
// R5: occupancy push. __launch_bounds__(256,5) caps regs at 51 -> 5 blocks/SM
// (40 warps, 62.5% occ) vs 4 blocks at 54 regs. rgb outputs stored directly
// from zr window regs (no temp arrays); 32-bit store offsets to cut IMAD chains.
// Keeps R4's warp-staged smem (__syncwarp only, minimal LDG redundancy).

#define IMG_W 3072
#define IMG_H 2048
#define SEG   1024
#define WSPAN 160            // floats staged per warp per array: [base-16, base+144)

__device__ __forceinline__
float4 ld4_guard(const float* __restrict__ row, int g)
{
    if (g >= 0 && g + 3 < IMG_W)
        return __ldg(reinterpret_cast<const float4*>(row + g));
    float t[4];
    #pragma unroll
    for (int j = 0; j < 4; ++j) {
        const int gg = g + j;
        t[j] = (gg >= 0 && gg < IMG_W) ? __ldg(row + gg) : 0.0f;
    }
    return make_float4(t[0], t[1], t[2], t[3]);
}

__global__ __launch_bounds__(256, 5)
void color_restore_kernel(const float* __restrict__ x,
                          const float* __restrict__ z,
                          float* __restrict__ out)
{
    __shared__ float sx[8][WSPAN];
    __shared__ float sz[8][WSPAN];

    const int h    = blockIdx.y;
    const int gw0  = blockIdx.x * SEG;
    const int t    = threadIdx.x;
    const int wid  = t >> 5;
    const int lane = t & 31;

    const unsigned rowoff = (unsigned)h * IMG_W;
    const float* __restrict__ xrow = x + rowoff;
    const float* __restrict__ zrow = z + rowoff;

    const int base = gw0 + (wid << 7);          // warp's first output column
    float* __restrict__ swx = sx[wid];
    float* __restrict__ swz = sz[wid];

    // ---- stage warp slice: 40 float4 chunks, chunk c at global base-16+4c ----
    const bool winterior = (base >= 16) && (base + 143 < IMG_W);
    if (winterior) {
        const float4 xv = __ldg(reinterpret_cast<const float4*>(xrow + base - 16 + 4 * lane));
        const float4 zv = __ldg(reinterpret_cast<const float4*>(zrow + base - 16 + 4 * lane));
        float4 xv2, zv2;
        if (lane < 8) {
            xv2 = __ldg(reinterpret_cast<const float4*>(xrow + base + 112 + 4 * lane));
            zv2 = __ldg(reinterpret_cast<const float4*>(zrow + base + 112 + 4 * lane));
        }
        reinterpret_cast<float4*>(swx)[lane] = xv;
        reinterpret_cast<float4*>(swz)[lane] = zv;
        if (lane < 8) {
            reinterpret_cast<float4*>(swx)[32 + lane] = xv2;
            reinterpret_cast<float4*>(swz)[32 + lane] = zv2;
        }
    } else {
        const float4 xv = ld4_guard(xrow, base - 16 + 4 * lane);
        const float4 zv = ld4_guard(zrow, base - 16 + 4 * lane);
        float4 xv2, zv2;
        if (lane < 8) {
            xv2 = ld4_guard(xrow, base + 112 + 4 * lane);
            zv2 = ld4_guard(zrow, base + 112 + 4 * lane);
        }
        reinterpret_cast<float4*>(swx)[lane] = xv;
        reinterpret_cast<float4*>(swz)[lane] = zv;
        if (lane < 8) {
            reinterpret_cast<float4*>(swx)[32 + lane] = xv2;
            reinterpret_cast<float4*>(swz)[32 + lane] = zv2;
        }
    }
    __syncwarp();

    // ---- per-thread windows from warp slice (w0 = base + 4*lane) ----
    const int sI = 16 + 4 * lane;

    // zr[j] = z[w0-16+j], j=0..19  (5 aligned LDS.128)
    float zr[20];
    #pragma unroll
    for (int q = 0; q < 5; ++q) {
        const float4 v = *reinterpret_cast<const float4*>(swz + (sI - 16) + 4 * q);
        zr[4*q+0] = v.x; zr[4*q+1] = v.y; zr[4*q+2] = v.z; zr[4*q+3] = v.w;
    }
    // xr[j] = x[w0-12+j], j=0..27  (7 aligned LDS.128)
    float xr[28];
    #pragma unroll
    for (int q = 0; q < 7; ++q) {
        const float4 v = *reinterpret_cast<const float4*>(swx + (sI - 12) + 4 * q);
        xr[4*q+0] = v.x; xr[4*q+1] = v.y; xr[4*q+2] = v.z; xr[4*q+3] = v.w;
    }

    // ---- rgb_filter planes come straight from zr (no temps) ----
    const unsigned HW    = (unsigned)IMG_H * IMG_W;
    const unsigned obase = rowoff + (unsigned)(base + 4 * lane);
    __stcs(reinterpret_cast<float4*>(out + 3u * HW + obase),
           make_float4(zr[13], zr[14], zr[15], zr[16]));
    __stcs(reinterpret_cast<float4*>(out + 4u * HW + obase),
           make_float4(zr[9], zr[10], zr[11], zr[12]));
    __stcs(reinterpret_cast<float4*>(out + 5u * HW + obase),
           make_float4(zr[6], zr[7], zr[8], zr[9]));

    // ---- init window sum ending at w0: u = w0-13+k, k=0..13 ----
    //   z[u] -> zr[3+k] ; x[u+3] -> xr[k+2] ; x[u+7] -> xr[k+6] ; x[u+10] -> xr[k+9]
    float den = 0.0f, n3 = 0.0f, n7 = 0.0f, n10 = 0.0f;
    #pragma unroll
    for (int k = 0; k < 14; ++k) {
        const float zu = zr[3 + k];
        den += zu;
        n3  = fmaf(xr[k + 2], zu, n3);
        n7  = fmaf(xr[k + 6], zu, n7);
        n10 = fmaf(xr[k + 9], zu, n10);
    }

    float y3a[4], y7a[4], y10a[4];
    {
        const float r = 1.0f / den;
        y3a[0] = n3 * r;  y7a[0] = n7 * r;  y10a[0] = n10 * r;
    }
    // slide: add u_new = w0+i (z=zr[16+i]), drop u_old = w0+i-14 (z=zr[2+i])
    #pragma unroll
    for (int i = 1; i < 4; ++i) {
        const float zn = zr[16 + i];
        const float zo = zr[2 + i];
        den += zn - zo;
        n3  = fmaf(xr[15 + i], zn, fmaf(-xr[1 + i], zo, n3));
        n7  = fmaf(xr[19 + i], zn, fmaf(-xr[5 + i], zo, n7));
        n10 = fmaf(xr[22 + i], zn, fmaf(-xr[8 + i], zo, n10));
        const float r = 1.0f / den;
        y3a[i] = n3 * r;   y7a[i] = n7 * r;   y10a[i] = n10 * r;
    }

    // ---- y stores ----
    __stcs(reinterpret_cast<float4*>(out + 0u * HW + obase), *reinterpret_cast<float4*>(y3a));
    __stcs(reinterpret_cast<float4*>(out + 1u * HW + obase), *reinterpret_cast<float4*>(y7a));
    __stcs(reinterpret_cast<float4*>(out + 2u * HW + obase), *reinterpret_cast<float4*>(y10a));
}

extern "C" void kernel_launch(void* const* d_in, const int* in_sizes, int n_in,
                              void* d_out, int out_size)
{
    (void)in_sizes; (void)n_in; (void)out_size;
    const float* x = (const float*)d_in[0];
    const float* z = (const float*)d_in[1];
    float* out = (float*)d_out;

    dim3 grid(IMG_W / SEG, IMG_H);   // (3, 2048)
    color_restore_kernel<<<grid, 256>>>(x, z, out);
}